// round 11
// baseline (speedup 1.0000x reference)
#include <cuda_runtime.h>
#include <math.h>
#include <stdint.h>

// LocalAtten: NI=128, ND=32, NH=4, nnei=120.
// Algebraic refactor (never materialize kv) + head-group execution:
//   p[t,h,c] = sum_d Q[t,d*4+h] * Wkv[c, d*4+h]
//   l[t,h,j] = gg1[t,j,:] . p[t,h,:]
//   a = softmax-mask-sw(l)
//   u[t,h,:] = sum_j a[t,h,j] * gg1[t,j,:]
//   out[t,:] = sum_h u[t,h,:] @ W2_h + bh,  W2_h = Wv_h @ Wh_h (precomputed)
// 4 groups of 4 warps; group h owns head h (logits->softmax->u) with
// group-local named barriers; ONE full __syncthreads per token.
// Packed fp32x2 FMA; mask-predicated gg1 DMA; W2 staged via cp.async.
// Race fix: full __syncthreads between token loop and Phase C (chunk-1
// cp.async targets the last token's gg1 buffer; all groups must be done).

#define NIc 128
#define NDc 32
#define NHc 4
#define NNEI 120
#define KVW ((NDc + NIc) * NHc) /* 640 */
#define TPC 14
#define NTHR 512
#define INV_SQRT_ND 0.17677669529663687f
#define UTP 20

typedef unsigned long long u64;

__device__ float W2g[NHc * NIc * NIc];

__device__ __forceinline__ u64 pk2(float x, float y) {
    u64 r;
    asm("mov.b64 %0, {%1,%2};" : "=l"(r) : "f"(x), "f"(y));
    return r;
}
__device__ __forceinline__ void up2(u64 v, float& x, float& y) {
    asm("mov.b64 {%0,%1}, %2;" : "=f"(x), "=f"(y) : "l"(v));
}
__device__ __forceinline__ void fma2(u64& d, u64 a, u64 b) {
    asm("fma.rn.f32x2 %0, %1, %2, %0;" : "+l"(d) : "l"(a), "l"(b));
}
#define BAR_GRP(id) asm volatile("bar.sync %0, %1;" ::"r"(id), "r"(128) : "memory")

// ---------------- prep: W2[h*128+c][o] = sum_i Wv_h[c,i] * Wh[h*128+i, o] ----
__global__ void prep_w2_kernel(const float* __restrict__ Wkv,
                               const float* __restrict__ Wh) {
    __shared__ float wk[4 * NIc];
    int b = blockIdx.x;
    int h = b >> 5, c0 = (b & 31) * 4;
    int o = threadIdx.x;
#pragma unroll
    for (int cc = 0; cc < 4; cc++)
        wk[cc * NIc + o] = Wkv[(size_t)(c0 + cc) * KVW + NDc * NHc + o * NHc + h];
    __syncthreads();
    float acc[4] = {0.f, 0.f, 0.f, 0.f};
#pragma unroll 8
    for (int i = 0; i < NIc; i++) {
        float w = Wh[(size_t)(h * NIc + i) * NIc + o];
        acc[0] += wk[0 * NIc + i] * w;
        acc[1] += wk[1 * NIc + i] * w;
        acc[2] += wk[2 * NIc + i] * w;
        acc[3] += wk[3 * NIc + i] * w;
    }
#pragma unroll
    for (int cc = 0; cc < 4; cc++)
        W2g[(size_t)(h * NIc + c0 + cc) * NIc + o] = acc[cc];
}

// ---------------- cp.async ----------------
__device__ __forceinline__ void cpa16(float* dst, const float* src) {
    unsigned d = (unsigned)__cvta_generic_to_shared(dst);
    asm volatile("cp.async.cg.shared.global [%0], [%1], 16;\n" ::"r"(d), "l"(src));
}
// Mask-predicated gg1 tile load: 4 threads per neighbor row (128B each).
__device__ __forceinline__ void load_gg1_tile_masked(float* buf, const float* src,
                                                     const float* mkrow, int tid) {
    int row = tid >> 2;
    int q = tid & 3;
    if (row < NNEI && mkrow[row] != 0.f) {
        const float* s = src + row * NIc + q * 32;
        float* d = buf + row * NIc + q * 32;
#pragma unroll
        for (int i = 0; i < 8; i++) cpa16(d + i * 4, s + i * 4);
    }
}
__device__ __forceinline__ void load_w2_chunk(float* buf, int chunk, int tid) {
#pragma unroll
    for (int q = 0; q < 4; q++) {
        int idx = tid + q * NTHR;
        cpa16(buf + idx * 4, &W2g[(size_t)chunk * 8192 + idx * 4]);
    }
}

// smem layout (floats)
#define OFF_GB0 0
#define OFF_GB1 15360
#define OFF_QS 30720   /* 14*128  = 1792 */
#define OFF_PS 32512   /* 14*512  = 7168 */
#define OFF_LA 39680   /* 4*128   = 512  (logits) */
#define OFF_AW 40192   /* 4*128   = 512  (attention weights) */
#define OFF_UT 40704   /* 512*20  = 10240 */
#define OFF_RED 50944  /* 2048 (u partials / G1 tile / C partials) */
#define OFF_SW 52992   /* 1680 */
#define OFF_MK 54672   /* 1680 */
#define SMEM_FLOATS 56352
#define SMEM_BYTES (SMEM_FLOATS * 4) /* 225408 */

__global__ __launch_bounds__(NTHR, 1) void localatten_kernel(
    const float* __restrict__ g1, const float* __restrict__ gg1,
    const void* __restrict__ maskp, const float* __restrict__ sw,
    const float* __restrict__ Wq, const float* __restrict__ Wkv,
    const float* __restrict__ bh, float* __restrict__ out, int ntok) {
    extern __shared__ __align__(16) float sm[];
    float* GB0 = sm + OFF_GB0;
    float* GB1 = sm + OFF_GB1;
    float* Qs  = sm + OFF_QS;
    float* Ps  = sm + OFF_PS;
    float* la  = sm + OFF_LA;   // [h*128 + j] logits
    float* aw  = sm + OFF_AW;   // [h*128 + j] attention weights
    float* Ut  = sm + OFF_UT;   // [k*UTP + t]
    float* red = sm + OFF_RED;
    float* SWs = sm + OFF_SW;
    float* Mk  = sm + OFF_MK;
    float* G1s = red;

    const int tid = threadIdx.x;
    const int tok0 = blockIdx.x * TPC;
    int tcount = ntok - tok0;
    if (tcount <= 0) return;
    if (tcount > TPC) tcount = TPC;
    const int nj = tcount * NNEI;

    // ---- mask dtype self-detection ----
    int mmode;
    {
        const int* mi = (const int*)maskp;
        bool word = true;
#pragma unroll 8
        for (int i = 0; i < 64; i++) {
            int v = mi[i];
            if (v != 0 && v != 1 && v != 0x3f800000) word = false;
        }
        mmode = word ? 0 : 1;
    }

    // ---- sw slice prefetch ----
    {
        const float* swsrc = sw + (size_t)tok0 * NNEI;
        int nq = nj / 4;
        for (int q = tid; q < nq; q += NTHR)
            cpa16(SWs + q * 4, swsrc + q * 4);
    }

    // ---- mask -> smem as 0/1 float ----
    {
        const size_t base = (size_t)tok0 * NNEI;
        if (mmode == 0) {
            const int* mi = (const int*)maskp + base;
            for (int i = tid; i < nj; i += NTHR) Mk[i] = (mi[i] != 0) ? 1.f : 0.f;
        } else {
            const unsigned char* mb = (const unsigned char*)maskp + base;
            for (int i = tid; i < nj; i += NTHR) Mk[i] = (mb[i] != 0) ? 1.f : 0.f;
        }
    }

    // ---- Phase A0: G1 tile (reuses red) ----
    for (int idx = tid; idx < tcount * NIc; idx += NTHR)
        G1s[idx] = g1[(size_t)tok0 * NIc + idx];
    __syncthreads();  // Mk + G1s visible

    // ---- tile 0 prefetch (mask-predicated); group: sw + tile0 ----
    load_gg1_tile_masked(GB0, gg1 + (size_t)tok0 * NNEI * NIc, &Mk[0], tid);
    asm volatile("cp.async.commit_group;\n");

    // ---- Phase A1: Q = G1 @ Wq ----
    {
        int grp = tid >> 7, x = tid & 127;
        float acc[4] = {0.f, 0.f, 0.f, 0.f};
#pragma unroll 2
        for (int i = 0; i < NIc; i++) {
            float w = Wq[(size_t)i * NIc + x];
#pragma unroll
            for (int g2 = 0; g2 < 4; g2++)
                acc[g2] += G1s[(grp * 4 + g2) * NIc + i] * w;
        }
#pragma unroll
        for (int g2 = 0; g2 < 4; g2++) {
            int t = grp * 4 + g2;
            if (t < tcount) Qs[t * NIc + x] = acc[g2];
        }
    }
    __syncthreads();

    // ---- Phase A2: P[t][h][c] ----
    {
        int grp = tid >> 7, c = tid & 127;
        u64 pac[4][2];
#pragma unroll
        for (int g2 = 0; g2 < 4; g2++) pac[g2][0] = pac[g2][1] = 0ull;
#pragma unroll 4
        for (int d = 0; d < NDc; d++) {
            ulonglong2 w = *(const ulonglong2*)&Wkv[(size_t)c * KVW + d * 4];
#pragma unroll
            for (int g2 = 0; g2 < 4; g2++) {
                ulonglong2 q = *(const ulonglong2*)&Qs[(grp * 4 + g2) * NIc + d * 4];
                fma2(pac[g2][0], q.x, w.x);
                fma2(pac[g2][1], q.y, w.y);
            }
        }
#pragma unroll
        for (int g2 = 0; g2 < 4; g2++) {
            int t = grp * 4 + g2;
            if (t < tcount) {
                float p0, p1, p2, p3;
                up2(pac[g2][0], p0, p1);
                up2(pac[g2][1], p2, p3);
                Ps[(t * 4 + 0) * NIc + c] = p0;
                Ps[(t * 4 + 1) * NIc + c] = p1;
                Ps[(t * 4 + 2) * NIc + c] = p2;
                Ps[(t * 4 + 3) * NIc + c] = p3;
            }
        }
    }
    __syncthreads();

    const int warp = tid >> 5, lane = tid & 31;
    const int hgrp = warp >> 2;  // head / group id 0..3
    const int wsub = warp & 3;   // warp within group
    const int sub = lane & 7, jg = lane >> 3;
    const unsigned gmask = 0xFFu << (jg * 8);
    const int bar_id = 1 + hgrp;

    // ---- Phase B: token loop. ONE full bar per token. ----
    for (int t = 0; t < tcount; t++) {
        asm volatile("cp.async.wait_group 0;\n");
        __syncthreads();  // tile t ready everywhere; everyone done with t-1

        // issue next tile (targets buffer of t-1, freed by the bar above)
        if (t + 1 < tcount)
            load_gg1_tile_masked((t & 1) ? GB0 : GB1,
                                 gg1 + (size_t)(tok0 + t + 1) * NNEI * NIc,
                                 &Mk[(t + 1) * NNEI], tid);
        else
            load_w2_chunk((tcount & 1) ? GB1 : GB0, 0, tid);
        asm volatile("cp.async.commit_group;\n");

        const float* g = (t & 1) ? GB1 : GB0;
        const float* mrow = &Mk[t * NNEI];

        // ---- logits for head hgrp: warp covers 4 j per pass, 8 passes ----
        {
            u64 ph[4][2];
#pragma unroll
            for (int k = 0; k < 4; k++) {
                ulonglong2 v = *(const ulonglong2*)&Ps[(t * 4 + hgrp) * NIc +
                                                       k * 32 + sub * 4];
                ph[k][0] = v.x;
                ph[k][1] = v.y;
            }
#pragma unroll
            for (int pass = 0; pass < 8; pass++) {
                int j = pass * 16 + wsub * 4 + jg;
                bool act = (j < NNEI) && (mrow[j] != 0.f);
                if (act) {
                    u64 s2 = 0ull;
#pragma unroll
                    for (int k = 0; k < 4; k++) {
                        ulonglong2 gv =
                            *(const ulonglong2*)&g[j * NIc + k * 32 + sub * 4];
                        fma2(s2, gv.x, ph[k][0]);
                        fma2(s2, gv.y, ph[k][1]);
                    }
                    float lo, hi;
                    up2(s2, lo, hi);
                    float s = lo + hi;
#pragma unroll
                    for (int off = 4; off >= 1; off >>= 1)
                        s += __shfl_xor_sync(gmask, s, off);
                    if (sub == 0) la[hgrp * NIc + j] = s;
                }
            }
        }
        BAR_GRP(bar_id);

        // ---- softmax head hgrp: all 4 warps compute redundantly;
        //      warp wsub writes quarter j in [wsub*32, wsub*32+32) to aw ----
        {
            float v[4];
            int mskv[4];
            float mx = -INFINITY;
#pragma unroll
            for (int q2 = 0; q2 < 4; q2++) {
                int j = lane + q2 * 32;
                bool in = j < NNEI;
                mskv[q2] = in ? (mrow[j] != 0.f) : 0;
                v[q2] = (in && mskv[q2]) ? la[hgrp * NIc + j] * INV_SQRT_ND
                                         : -INFINITY;
                mx = fmaxf(mx, v[q2]);
            }
#pragma unroll
            for (int off = 16; off >= 1; off >>= 1)
                mx = fmaxf(mx, __shfl_xor_sync(0xffffffffu, mx, off));
            float e[4];
            float s = 0.f;
#pragma unroll
            for (int q2 = 0; q2 < 4; q2++) {
                e[q2] = mskv[q2] ? __expf(v[q2] - mx) : 0.f;
                s += e[q2];
            }
#pragma unroll
            for (int off = 16; off >= 1; off >>= 1)
                s += __shfl_xor_sync(0xffffffffu, s, off);
            float inv = (s > 0.f) ? (1.f / s) : 0.f;
            int jw = lane + wsub * 32;
            if (jw < NNEI)
                aw[hgrp * NIc + jw] = e[wsub] * inv * SWs[t * NNEI + jw];
        }
        BAR_GRP(bar_id);

        // ---- u for head hgrp: warp wsub owns j in [wsub*30, wsub*30+30) ----
        {
            u64 ua0 = 0ull, ua1 = 0ull;
            const int j0 = wsub * 30;
            const float* awb = aw + hgrp * NIc + j0;
            const float* gb = g + (size_t)j0 * NIc + lane * 4;
#pragma unroll 5
            for (int jj = 0; jj < 30; jj++) {
                float a = awb[jj];
                if (a == 0.f) continue;
                ulonglong2 gv = *(const ulonglong2*)(gb + jj * NIc);
                u64 ad = pk2(a, a);
                fma2(ua0, gv.x, ad);
                fma2(ua1, gv.y, ad);
            }
            ulonglong2 st;
            st.x = ua0;
            st.y = ua1;
            *(ulonglong2*)&red[(hgrp * 4 + wsub) * NIc + lane * 4] = st;
        }
        BAR_GRP(bar_id);

        // ---- Ut[k][t] for k in [hgrp*128, hgrp*128+128): group's 128 thr ----
        {
            int kl = tid & 127;
            float s = red[(hgrp * 4 + 0) * NIc + kl] +
                      red[(hgrp * 4 + 1) * NIc + kl] +
                      red[(hgrp * 4 + 2) * NIc + kl] +
                      red[(hgrp * 4 + 3) * NIc + kl];
            Ut[(hgrp * NIc + kl) * UTP + t] = s;
        }
        // no full bar here: next iteration's top bar is the convergence point
    }

    // RACE FIX: all groups must finish reading the last gg1 buffer before
    // Phase C's chunk-1 cp.async overwrites it.
    __syncthreads();

    // ---- Phase C: OUT[t][o] = bh[o] + sum_k Ut[k][t] * W2[k][o] ----
    {
        const int o = tid & 127;
        const int tg = (tid >> 7) & 1;
        const int kh = tid >> 8;
        u64 acc[4] = {0ull, 0ull, 0ull, 0ull};
#pragma unroll 1
        for (int c = 0; c < 8; c++) {
            float* wbuf = ((tcount + c) & 1) ? GB1 : GB0;
            if (c + 1 < 8) {
                load_w2_chunk(((tcount + c + 1) & 1) ? GB1 : GB0, c + 1, tid);
                asm volatile("cp.async.commit_group;\n");
                asm volatile("cp.async.wait_group 1;\n");
            } else {
                asm volatile("cp.async.wait_group 0;\n");
            }
            __syncthreads();
            const float* wrow = wbuf + kh * 32 * NIc + o;
            const float* urow = &Ut[(c * 64 + kh * 32) * UTP + tg * 8];
#pragma unroll 8
            for (int kk = 0; kk < 32; kk++) {
                float w = wrow[kk * NIc];
                u64 wd = pk2(w, w);
                ulonglong2 uA = *(const ulonglong2*)(urow + kk * UTP);
                ulonglong2 uB = *(const ulonglong2*)(urow + kk * UTP + 4);
                fma2(acc[0], uA.x, wd);
                fma2(acc[1], uA.y, wd);
                fma2(acc[2], uB.x, wd);
                fma2(acc[3], uB.y, wd);
            }
            __syncthreads();  // protect wbuf before it becomes a prefetch target
        }

        if (kh == 1) {
            ulonglong2 s0, s1;
            s0.x = acc[0]; s0.y = acc[1];
            s1.x = acc[2]; s1.y = acc[3];
            *(ulonglong2*)&red[(tid & 255) * 8] = s0;
            *(ulonglong2*)&red[(tid & 255) * 8 + 4] = s1;
        }
        __syncthreads();
        if (kh == 0) {
            float b = bh[o];
            const float* pr = &red[(tid & 255) * 8];
            float v[8];
            up2(acc[0], v[0], v[1]);
            up2(acc[1], v[2], v[3]);
            up2(acc[2], v[4], v[5]);
            up2(acc[3], v[6], v[7]);
#pragma unroll
            for (int tt = 0; tt < 8; tt++) {
                int t = tg * 8 + tt;
                if (t < tcount)
                    out[(size_t)(tok0 + t) * NIc + o] = v[tt] + pr[tt] + b;
            }
        }
    }
}

extern "C" void kernel_launch(void* const* d_in, const int* in_sizes, int n_in,
                              void* d_out, int out_size) {
    const float* g1  = (const float*)d_in[0];
    const float* gg1 = (const float*)d_in[1];
    const void*  msk = d_in[2];
    const float* sw  = (const float*)d_in[3];
    const float* Wq  = (const float*)d_in[4];
    const float* Wkv = (const float*)d_in[5];
    const float* Wh  = (const float*)d_in[6];
    const float* bh  = (const float*)d_in[7];
    float* out = (float*)d_out;

    int ntok = in_sizes[0] / NIc;  // nb*nloc

    prep_w2_kernel<<<128, 128>>>(Wkv, Wh);

    cudaFuncSetAttribute(localatten_kernel,
                         cudaFuncAttributeMaxDynamicSharedMemorySize, SMEM_BYTES);
    int grid = (ntok + TPC - 1) / TPC;
    localatten_kernel<<<grid, NTHR, SMEM_BYTES>>>(g1, gg1, msk, sw, Wq, Wkv, bh,
                                                  out, ntok);
}

// round 14
// speedup vs baseline: 1.0847x; 1.0847x over previous
#include <cuda_runtime.h>
#include <math.h>
#include <stdint.h>

// LocalAtten: NI=128, ND=32, NH=4, nnei=120.
// Algebraic refactor (never materialize kv) + head-group execution:
//   p[t,h,c] = sum_d Q[t,d*4+h] * Wkv[c, d*4+h]
//   l[t,h,j] = gg1[t,j,:] . p[t,h,:]
//   a = softmax-mask-sw(l)
//   u[t,h,:] = sum_j a[t,h,j] * gg1[t,j,:]
//   out[t,:] = sum_h u[t,h,:] @ W2_h + bh,  W2_h = Wv_h @ Wh_h (precomputed)
// 4 groups of 4 warps; group h owns head h; ONE full __syncthreads per token.
// R12 fix: gg1 DMA re-coalesced — one cp.async instruction per neighbor row
// (32 lanes x 16B = 512B contiguous) instead of the previous 4-threads-per-row
// scatter that generated ~32 L1TEX wavefronts per instruction (8x waste).

#define NIc 128
#define NDc 32
#define NHc 4
#define NNEI 120
#define KVW ((NDc + NIc) * NHc) /* 640 */
#define TPC 14
#define NTHR 512
#define INV_SQRT_ND 0.17677669529663687f
#define UTP 20

typedef unsigned long long u64;

__device__ float W2g[NHc * NIc * NIc];

__device__ __forceinline__ u64 pk2(float x, float y) {
    u64 r;
    asm("mov.b64 %0, {%1,%2};" : "=l"(r) : "f"(x), "f"(y));
    return r;
}
__device__ __forceinline__ void up2(u64 v, float& x, float& y) {
    asm("mov.b64 {%0,%1}, %2;" : "=f"(x), "=f"(y) : "l"(v));
}
__device__ __forceinline__ void fma2(u64& d, u64 a, u64 b) {
    asm("fma.rn.f32x2 %0, %1, %2, %0;" : "+l"(d) : "l"(a), "l"(b));
}
#define BAR_GRP(id) asm volatile("bar.sync %0, %1;" ::"r"(id), "r"(128) : "memory")

// ---------------- prep: W2[h*128+c][o] = sum_i Wv_h[c,i] * Wh[h*128+i, o] ----
__global__ void prep_w2_kernel(const float* __restrict__ Wkv,
                               const float* __restrict__ Wh) {
    __shared__ float wk[4 * NIc];
    int b = blockIdx.x;
    int h = b >> 5, c0 = (b & 31) * 4;
    int o = threadIdx.x;
#pragma unroll
    for (int cc = 0; cc < 4; cc++)
        wk[cc * NIc + o] = Wkv[(size_t)(c0 + cc) * KVW + NDc * NHc + o * NHc + h];
    __syncthreads();
    float acc[4] = {0.f, 0.f, 0.f, 0.f};
#pragma unroll 8
    for (int i = 0; i < NIc; i++) {
        float w = Wh[(size_t)(h * NIc + i) * NIc + o];
        acc[0] += wk[0 * NIc + i] * w;
        acc[1] += wk[1 * NIc + i] * w;
        acc[2] += wk[2 * NIc + i] * w;
        acc[3] += wk[3 * NIc + i] * w;
    }
#pragma unroll
    for (int cc = 0; cc < 4; cc++)
        W2g[(size_t)(h * NIc + c0 + cc) * NIc + o] = acc[cc];
}

// ---------------- cp.async ----------------
__device__ __forceinline__ void cpa16(float* dst, const float* src) {
    unsigned d = (unsigned)__cvta_generic_to_shared(dst);
    asm volatile("cp.async.cg.shared.global [%0], [%1], 16;\n" ::"r"(d), "l"(src));
}
// Mask-predicated gg1 tile load, warp-coalesced: warp w owns rows 8w..8w+7;
// each row is ONE cp.async instruction (32 lanes x 16B = 512B contiguous).
// Masked rows are skipped (their stale smem contents are never consumed).
__device__ __forceinline__ void load_gg1_tile_masked(float* buf, const float* src,
                                                     const float* mkrow, int tid) {
    int w = tid >> 5, lane = tid & 31;
    if (w < 15) {
#pragma unroll
        for (int i = 0; i < 8; i++) {
            int row = w * 8 + i;
            if (mkrow[row] != 0.f)
                cpa16(buf + row * NIc + lane * 4, src + (size_t)row * NIc + lane * 4);
        }
    }
}
__device__ __forceinline__ void load_w2_chunk(float* buf, int chunk, int tid) {
#pragma unroll
    for (int q = 0; q < 4; q++) {
        int idx = tid + q * NTHR;
        cpa16(buf + idx * 4, &W2g[(size_t)chunk * 8192 + idx * 4]);
    }
}

// smem layout (floats)
#define OFF_GB0 0
#define OFF_GB1 15360
#define OFF_QS 30720   /* 14*128  = 1792 */
#define OFF_PS 32512   /* 14*512  = 7168 */
#define OFF_LA 39680   /* 4*128   = 512  (logits) */
#define OFF_AW 40192   /* 4*128   = 512  (attention weights) */
#define OFF_UT 40704   /* 512*20  = 10240 */
#define OFF_RED 50944  /* 2048 (u partials / G1 tile / C partials) */
#define OFF_SW 52992   /* 1680 */
#define OFF_MK 54672   /* 1680 */
#define SMEM_FLOATS 56352
#define SMEM_BYTES (SMEM_FLOATS * 4) /* 225408 */

__global__ __launch_bounds__(NTHR, 1) void localatten_kernel(
    const float* __restrict__ g1, const float* __restrict__ gg1,
    const void* __restrict__ maskp, const float* __restrict__ sw,
    const float* __restrict__ Wq, const float* __restrict__ Wkv,
    const float* __restrict__ bh, float* __restrict__ out, int ntok) {
    extern __shared__ __align__(16) float sm[];
    float* GB0 = sm + OFF_GB0;
    float* GB1 = sm + OFF_GB1;
    float* Qs  = sm + OFF_QS;
    float* Ps  = sm + OFF_PS;
    float* la  = sm + OFF_LA;   // [h*128 + j] logits
    float* aw  = sm + OFF_AW;   // [h*128 + j] attention weights
    float* Ut  = sm + OFF_UT;   // [k*UTP + t]
    float* red = sm + OFF_RED;
    float* SWs = sm + OFF_SW;
    float* Mk  = sm + OFF_MK;
    float* G1s = red;

    const int tid = threadIdx.x;
    const int tok0 = blockIdx.x * TPC;
    int tcount = ntok - tok0;
    if (tcount <= 0) return;
    if (tcount > TPC) tcount = TPC;
    const int nj = tcount * NNEI;

    // ---- mask dtype self-detection ----
    int mmode;
    {
        const int* mi = (const int*)maskp;
        bool word = true;
#pragma unroll 8
        for (int i = 0; i < 64; i++) {
            int v = mi[i];
            if (v != 0 && v != 1 && v != 0x3f800000) word = false;
        }
        mmode = word ? 0 : 1;
    }

    // ---- sw slice prefetch ----
    {
        const float* swsrc = sw + (size_t)tok0 * NNEI;
        int nq = nj / 4;
        for (int q = tid; q < nq; q += NTHR)
            cpa16(SWs + q * 4, swsrc + q * 4);
    }

    // ---- mask -> smem as 0/1 float ----
    {
        const size_t base = (size_t)tok0 * NNEI;
        if (mmode == 0) {
            const int* mi = (const int*)maskp + base;
            for (int i = tid; i < nj; i += NTHR) Mk[i] = (mi[i] != 0) ? 1.f : 0.f;
        } else {
            const unsigned char* mb = (const unsigned char*)maskp + base;
            for (int i = tid; i < nj; i += NTHR) Mk[i] = (mb[i] != 0) ? 1.f : 0.f;
        }
    }

    // ---- Phase A0: G1 tile (reuses red) ----
    for (int idx = tid; idx < tcount * NIc; idx += NTHR)
        G1s[idx] = g1[(size_t)tok0 * NIc + idx];
    __syncthreads();  // Mk + G1s visible

    // ---- tile 0 prefetch (mask-predicated, coalesced); group: sw + tile0 ----
    load_gg1_tile_masked(GB0, gg1 + (size_t)tok0 * NNEI * NIc, &Mk[0], tid);
    asm volatile("cp.async.commit_group;\n");

    // ---- Phase A1: Q = G1 @ Wq ----
    {
        int grp = tid >> 7, x = tid & 127;
        float acc[4] = {0.f, 0.f, 0.f, 0.f};
#pragma unroll 2
        for (int i = 0; i < NIc; i++) {
            float w = Wq[(size_t)i * NIc + x];
#pragma unroll
            for (int g2 = 0; g2 < 4; g2++)
                acc[g2] += G1s[(grp * 4 + g2) * NIc + i] * w;
        }
#pragma unroll
        for (int g2 = 0; g2 < 4; g2++) {
            int t = grp * 4 + g2;
            if (t < tcount) Qs[t * NIc + x] = acc[g2];
        }
    }
    __syncthreads();

    // ---- Phase A2: P[t][h][c] ----
    {
        int grp = tid >> 7, c = tid & 127;
        u64 pac[4][2];
#pragma unroll
        for (int g2 = 0; g2 < 4; g2++) pac[g2][0] = pac[g2][1] = 0ull;
#pragma unroll 4
        for (int d = 0; d < NDc; d++) {
            ulonglong2 w = *(const ulonglong2*)&Wkv[(size_t)c * KVW + d * 4];
#pragma unroll
            for (int g2 = 0; g2 < 4; g2++) {
                ulonglong2 q = *(const ulonglong2*)&Qs[(grp * 4 + g2) * NIc + d * 4];
                fma2(pac[g2][0], q.x, w.x);
                fma2(pac[g2][1], q.y, w.y);
            }
        }
#pragma unroll
        for (int g2 = 0; g2 < 4; g2++) {
            int t = grp * 4 + g2;
            if (t < tcount) {
                float p0, p1, p2, p3;
                up2(pac[g2][0], p0, p1);
                up2(pac[g2][1], p2, p3);
                Ps[(t * 4 + 0) * NIc + c] = p0;
                Ps[(t * 4 + 1) * NIc + c] = p1;
                Ps[(t * 4 + 2) * NIc + c] = p2;
                Ps[(t * 4 + 3) * NIc + c] = p3;
            }
        }
    }
    __syncthreads();

    const int warp = tid >> 5, lane = tid & 31;
    const int hgrp = warp >> 2;  // head / group id 0..3
    const int wsub = warp & 3;   // warp within group
    const int sub = lane & 7, jg = lane >> 3;
    const unsigned gmask = 0xFFu << (jg * 8);
    const int bar_id = 1 + hgrp;

    // ---- Phase B: token loop. ONE full bar per token. ----
    for (int t = 0; t < tcount; t++) {
        asm volatile("cp.async.wait_group 0;\n");
        __syncthreads();  // tile t ready everywhere; everyone done with t-1

        // issue next tile (targets buffer of t-1, freed by the bar above)
        if (t + 1 < tcount)
            load_gg1_tile_masked((t & 1) ? GB0 : GB1,
                                 gg1 + (size_t)(tok0 + t + 1) * NNEI * NIc,
                                 &Mk[(t + 1) * NNEI], tid);
        else
            load_w2_chunk((tcount & 1) ? GB1 : GB0, 0, tid);
        asm volatile("cp.async.commit_group;\n");

        const float* g = (t & 1) ? GB1 : GB0;
        const float* mrow = &Mk[t * NNEI];

        // ---- logits for head hgrp: warp covers 4 j per pass, 8 passes ----
        {
            u64 ph[4][2];
#pragma unroll
            for (int k = 0; k < 4; k++) {
                ulonglong2 v = *(const ulonglong2*)&Ps[(t * 4 + hgrp) * NIc +
                                                       k * 32 + sub * 4];
                ph[k][0] = v.x;
                ph[k][1] = v.y;
            }
#pragma unroll
            for (int pass = 0; pass < 8; pass++) {
                int j = pass * 16 + wsub * 4 + jg;
                bool act = (j < NNEI) && (mrow[j] != 0.f);
                if (act) {
                    u64 s2 = 0ull;
#pragma unroll
                    for (int k = 0; k < 4; k++) {
                        ulonglong2 gv =
                            *(const ulonglong2*)&g[j * NIc + k * 32 + sub * 4];
                        fma2(s2, gv.x, ph[k][0]);
                        fma2(s2, gv.y, ph[k][1]);
                    }
                    float lo, hi;
                    up2(s2, lo, hi);
                    float s = lo + hi;
#pragma unroll
                    for (int off = 4; off >= 1; off >>= 1)
                        s += __shfl_xor_sync(gmask, s, off);
                    if (sub == 0) la[hgrp * NIc + j] = s;
                }
            }
        }
        BAR_GRP(bar_id);

        // ---- softmax head hgrp: all 4 warps compute redundantly;
        //      warp wsub writes quarter j in [wsub*32, wsub*32+32) to aw ----
        {
            float v[4];
            int mskv[4];
            float mx = -INFINITY;
#pragma unroll
            for (int q2 = 0; q2 < 4; q2++) {
                int j = lane + q2 * 32;
                bool in = j < NNEI;
                mskv[q2] = in ? (mrow[j] != 0.f) : 0;
                v[q2] = (in && mskv[q2]) ? la[hgrp * NIc + j] * INV_SQRT_ND
                                         : -INFINITY;
                mx = fmaxf(mx, v[q2]);
            }
#pragma unroll
            for (int off = 16; off >= 1; off >>= 1)
                mx = fmaxf(mx, __shfl_xor_sync(0xffffffffu, mx, off));
            float e[4];
            float s = 0.f;
#pragma unroll
            for (int q2 = 0; q2 < 4; q2++) {
                e[q2] = mskv[q2] ? __expf(v[q2] - mx) : 0.f;
                s += e[q2];
            }
#pragma unroll
            for (int off = 16; off >= 1; off >>= 1)
                s += __shfl_xor_sync(0xffffffffu, s, off);
            float inv = (s > 0.f) ? (1.f / s) : 0.f;
            int jw = lane + wsub * 32;
            if (jw < NNEI)
                aw[hgrp * NIc + jw] = e[wsub] * inv * SWs[t * NNEI + jw];
        }
        BAR_GRP(bar_id);

        // ---- u for head hgrp: warp wsub owns j in [wsub*30, wsub*30+30) ----
        {
            u64 ua0 = 0ull, ua1 = 0ull;
            const int j0 = wsub * 30;
            const float* awb = aw + hgrp * NIc + j0;
            const float* gb = g + (size_t)j0 * NIc + lane * 4;
#pragma unroll 5
            for (int jj = 0; jj < 30; jj++) {
                float a = awb[jj];
                if (a == 0.f) continue;
                ulonglong2 gv = *(const ulonglong2*)(gb + jj * NIc);
                u64 ad = pk2(a, a);
                fma2(ua0, gv.x, ad);
                fma2(ua1, gv.y, ad);
            }
            ulonglong2 st;
            st.x = ua0;
            st.y = ua1;
            *(ulonglong2*)&red[(hgrp * 4 + wsub) * NIc + lane * 4] = st;
        }
        BAR_GRP(bar_id);

        // ---- Ut[k][t] for k in [hgrp*128, hgrp*128+128): group's 128 thr ----
        {
            int kl = tid & 127;
            float s = red[(hgrp * 4 + 0) * NIc + kl] +
                      red[(hgrp * 4 + 1) * NIc + kl] +
                      red[(hgrp * 4 + 2) * NIc + kl] +
                      red[(hgrp * 4 + 3) * NIc + kl];
            Ut[(hgrp * NIc + kl) * UTP + t] = s;
        }
        // no full bar here: next iteration's top bar is the convergence point
    }

    // RACE FIX: all groups must finish reading the last gg1 buffer before
    // Phase C's chunk-1 cp.async overwrites it.
    __syncthreads();

    // ---- Phase C: OUT[t][o] = bh[o] + sum_k Ut[k][t] * W2[k][o] ----
    {
        const int o = tid & 127;
        const int tg = (tid >> 7) & 1;
        const int kh = tid >> 8;
        u64 acc[4] = {0ull, 0ull, 0ull, 0ull};
#pragma unroll 1
        for (int c = 0; c < 8; c++) {
            float* wbuf = ((tcount + c) & 1) ? GB1 : GB0;
            if (c + 1 < 8) {
                load_w2_chunk(((tcount + c + 1) & 1) ? GB1 : GB0, c + 1, tid);
                asm volatile("cp.async.commit_group;\n");
                asm volatile("cp.async.wait_group 1;\n");
            } else {
                asm volatile("cp.async.wait_group 0;\n");
            }
            __syncthreads();
            const float* wrow = wbuf + kh * 32 * NIc + o;
            const float* urow = &Ut[(c * 64 + kh * 32) * UTP + tg * 8];
#pragma unroll 8
            for (int kk = 0; kk < 32; kk++) {
                float w = wrow[kk * NIc];
                u64 wd = pk2(w, w);
                ulonglong2 uA = *(const ulonglong2*)(urow + kk * UTP);
                ulonglong2 uB = *(const ulonglong2*)(urow + kk * UTP + 4);
                fma2(acc[0], uA.x, wd);
                fma2(acc[1], uA.y, wd);
                fma2(acc[2], uB.x, wd);
                fma2(acc[3], uB.y, wd);
            }
            __syncthreads();  // protect wbuf before it becomes a prefetch target
        }

        if (kh == 1) {
            ulonglong2 s0, s1;
            s0.x = acc[0]; s0.y = acc[1];
            s1.x = acc[2]; s1.y = acc[3];
            *(ulonglong2*)&red[(tid & 255) * 8] = s0;
            *(ulonglong2*)&red[(tid & 255) * 8 + 4] = s1;
        }
        __syncthreads();
        if (kh == 0) {
            float b = bh[o];
            const float* pr = &red[(tid & 255) * 8];
            float v[8];
            up2(acc[0], v[0], v[1]);
            up2(acc[1], v[2], v[3]);
            up2(acc[2], v[4], v[5]);
            up2(acc[3], v[6], v[7]);
#pragma unroll
            for (int tt = 0; tt < 8; tt++) {
                int t = tg * 8 + tt;
                if (t < tcount)
                    out[(size_t)(tok0 + t) * NIc + o] = v[tt] + pr[tt] + b;
            }
        }
    }
}

extern "C" void kernel_launch(void* const* d_in, const int* in_sizes, int n_in,
                              void* d_out, int out_size) {
    const float* g1  = (const float*)d_in[0];
    const float* gg1 = (const float*)d_in[1];
    const void*  msk = d_in[2];
    const float* sw  = (const float*)d_in[3];
    const float* Wq  = (const float*)d_in[4];
    const float* Wkv = (const float*)d_in[5];
    const float* Wh  = (const float*)d_in[6];
    const float* bh  = (const float*)d_in[7];
    float* out = (float*)d_out;

    int ntok = in_sizes[0] / NIc;  // nb*nloc

    prep_w2_kernel<<<128, 128>>>(Wkv, Wh);

    cudaFuncSetAttribute(localatten_kernel,
                         cudaFuncAttributeMaxDynamicSharedMemorySize, SMEM_BYTES);
    int grid = (ntok + TPC - 1) / TPC;
    localatten_kernel<<<grid, NTHR, SMEM_BYTES>>>(g1, gg1, msk, sw, Wq, Wkv, bh,
                                                  out, ntok);
}